// round 3
// baseline (speedup 1.0000x reference)
#include <cuda_runtime.h>
#include <cuda_bf16.h>
#include <cstdint>

// VectorQuantizer forward — mma.sync (HMMA) edition, 3-split bf16 compensated.
// Inputs:  d_in[0] = x      [32, 64, 32, 32] fp32
//          d_in[1] = emb_w  [1024, 64]       fp32
// Output fp32: [0..2097151] out, [2097152] vq_loss, [2097153] perplexity,
//              [2097154..] encoded one-hot [32768, 1024]

#define NVEC   32768
#define KCODES 1024
#define DDIM   64
#define GEPS   2e-5f

// ---------------- device globals ---------------------------------------------
__device__ float g_en[KCODES];
__device__ int   g_counts[KCODES];
__device__ float g_mse;
__device__ int   g_idx[NVEC];
__device__ float g_rn[NVEC];
__device__ int   g_nflag;
__device__ int   g_flaglist[NVEC];
// emb bf16 hi/lo, pre-swizzled per 128-code chunk image (8 images x 16KB each)
__device__ uint4 g_ehi4[8192];
__device__ uint4 g_elo4[8192];

__device__ __forceinline__ uint32_t smem_u32(const void* p) {
    uint32_t a;
    asm("{ .reg .u64 t; cvta.to.shared.u64 t, %1; cvt.u32.u64 %0, t; }" : "=r"(a) : "l"(p));
    return a;
}
__device__ __forceinline__ uint32_t swz(uint32_t off) { return off ^ ((off >> 3) & 0x70); }

__device__ __forceinline__ void ldsm4(uint32_t a, uint32_t& r0, uint32_t& r1,
                                      uint32_t& r2, uint32_t& r3) {
    asm volatile("ldmatrix.sync.aligned.m8n8.x4.shared.b16 {%0,%1,%2,%3}, [%4];"
                 : "=r"(r0), "=r"(r1), "=r"(r2), "=r"(r3) : "r"(a));
}
__device__ __forceinline__ void mma_bf16(float& d0, float& d1, float& d2, float& d3,
                                         uint32_t a0, uint32_t a1, uint32_t a2, uint32_t a3,
                                         uint32_t b0, uint32_t b1) {
    asm volatile("mma.sync.aligned.m16n8k16.row.col.f32.bf16.bf16.f32 "
                 "{%0,%1,%2,%3}, {%4,%5,%6,%7}, {%8,%9}, {%0,%1,%2,%3};"
                 : "+f"(d0), "+f"(d1), "+f"(d2), "+f"(d3)
                 : "r"(a0), "r"(a1), "r"(a2), "r"(a3), "r"(b0), "r"(b1));
}
__device__ __forceinline__ void bf16split(float v, uint16_t& h, uint16_t& l) {
    __nv_bfloat16 hb = __float2bfloat16(v);
    __nv_bfloat16 lb = __float2bfloat16(v - __bfloat162float(hb));
    h = __bfloat16_as_ushort(hb);
    l = __bfloat16_as_ushort(lb);
}

// smem layout (dynamic, 1KB aligned): x_hi 16K | x_lo 16K | e_hi 16K | e_lo 16K
#define XHI 0
#define XLO 16384
#define EH  32768
#define EL  49152
#define DYNSM 65536

// ---- K1: emb -> bf16 hi/lo pre-swizzled chunk images; ||e||^2; zero accums --
__global__ __launch_bounds__(128) void vq_prep(const float* __restrict__ emb) {
    int t = threadIdx.x;
    int code = blockIdx.x * 16 + (t >> 3);
    int ch = t & 7;                               // 16B chunk (8 d's)
    const float* e = emb + code * DDIM + ch * 8;
    float4 a = *(const float4*)e, b = *(const float4*)(e + 4);
    float v[8] = {a.x, a.y, a.z, a.w, b.x, b.y, b.z, b.w};
    float s = 0.f;
    uint32_t hw[4], lw[4];
#pragma unroll
    for (int p = 0; p < 4; p++) {
        float v0 = v[2 * p], v1 = v[2 * p + 1];
        s = fmaf(v0, v0, s); s = fmaf(v1, v1, s);
        uint16_t h0, l0, h1, l1;
        bf16split(v0, h0, l0); bf16split(v1, h1, l1);
        hw[p] = (uint32_t)h0 | ((uint32_t)h1 << 16);
        lw[p] = (uint32_t)l0 | ((uint32_t)l1 << 16);
    }
    uint32_t off = (uint32_t)(code >> 7) * 1024u +
                   (swz((uint32_t)(code & 127) * 128u + (uint32_t)ch * 16u) >> 4);
    g_ehi4[off] = make_uint4(hw[0], hw[1], hw[2], hw[3]);
    g_elo4[off] = make_uint4(lw[0], lw[1], lw[2], lw[3]);
    s += __shfl_xor_sync(0xFFFFFFFFu, s, 1);
    s += __shfl_xor_sync(0xFFFFFFFFu, s, 2);
    s += __shfl_xor_sync(0xFFFFFFFFu, s, 4);
    if (ch == 0) { g_en[code] = s; g_counts[code] = 0; }
    if (blockIdx.x == 0 && t == 0) { g_mse = 0.f; g_nflag = 0; }
}

// ---- K2: HMMA GEMM (3-split bf16) + argmin + gap flag + encoded store -------
__global__ __launch_bounds__(256, 1) void vq_gemm(const float* __restrict__ x,
                                                  float* __restrict__ enc) {
    extern __shared__ __align__(1024) char dsm[];
    __shared__ float sval[4][128];
    __shared__ float ssec[4][128];
    __shared__ int   sidxr[4][128];
    __shared__ int   sidxf[128];
    __shared__ float srn[256];

    const int t = threadIdx.x;
    const int l = t & 31;
    const int wid = t >> 5;
    const int mg = wid >> 2;       // 0,1  -> rows mg*64
    const int ng = wid & 3;        // 0..3 -> cols ng*32 within each 128-chunk
    const int n0 = blockIdx.x * 128;
    const int b  = blockIdx.x >> 3;
    const int hw0 = (blockIdx.x & 7) * 128;

    const uint32_t sb = smem_u32(dsm);

    // ---- stage x: 2 threads per row (halves), bf16 split, swizzled ----------
    {
        int row = t & 127, half = t >> 7;
        const float* xb = x + (size_t)b * 65536 + hw0 + row;
        float rp = 0.f;
#pragma unroll
        for (int jj = 0; jj < 4; jj++) {
            int j = half * 4 + jj;
            float v[8];
#pragma unroll
            for (int i = 0; i < 8; i++) v[i] = xb[(size_t)(j * 8 + i) * 1024];
#pragma unroll
            for (int i = 0; i < 8; i++) rp = fmaf(v[i], v[i], rp);
            uint32_t hw_[4], lw_[4];
#pragma unroll
            for (int p = 0; p < 4; p++) {
                uint16_t h0, l0, h1, l1;
                bf16split(v[2 * p], h0, l0); bf16split(v[2 * p + 1], h1, l1);
                hw_[p] = (uint32_t)h0 | ((uint32_t)h1 << 16);
                lw_[p] = (uint32_t)l0 | ((uint32_t)l1 << 16);
            }
            uint32_t off = swz((uint32_t)row * 128u + (uint32_t)j * 16u);
            *(uint4*)(dsm + XHI + off) = make_uint4(hw_[0], hw_[1], hw_[2], hw_[3]);
            *(uint4*)(dsm + XLO + off) = make_uint4(lw_[0], lw_[1], lw_[2], lw_[3]);
        }
        srn[t] = rp;
    }
    __syncthreads();
    if (t < 128) g_rn[n0 + t] = srn[t] + srn[t + 128];

    // per-lane invariant ldmatrix address parts
    const uint32_t a_row = (uint32_t)((l & 7) + ((l >> 3) & 1) * 8);
    const uint32_t a_cadd = (uint32_t)(l >> 4);
    const uint32_t b_row = (uint32_t)(ng * 32 + (l & 7));
    const uint32_t b_cadd = (uint32_t)(l >> 3);

    float bestd[8], best2[8];
    int   bestk[8];
#pragma unroll
    for (int s = 0; s < 8; s++) { bestd[s] = 3.4e38f; best2[s] = 3.4e38f; bestk[s] = 0; }

#pragma unroll 1
    for (int c = 0; c < 8; c++) {
        __syncthreads();
        {   // stage 128-code chunk (pre-swizzled -> straight uint4 copies)
            const uint4* shh = g_ehi4 + c * 1024;
            const uint4* sll = g_elo4 + c * 1024;
            uint4* dh = (uint4*)(dsm + EH);
            uint4* dl = (uint4*)(dsm + EL);
#pragma unroll
            for (int i = 0; i < 4; i++) { dh[t + 256 * i] = shh[t + 256 * i];
                                          dl[t + 256 * i] = sll[t + 256 * i]; }
        }
        __syncthreads();

        // B fragments for this warp's 32 columns: [sp][ns][ks][2]
        uint32_t B[2][4][4][2];
#pragma unroll
        for (int sp = 0; sp < 2; sp++) {
            uint32_t base = sb + (sp ? EL : EH);
#pragma unroll
            for (int ns = 0; ns < 4; ns++) {
#pragma unroll
                for (int h = 0; h < 2; h++) {
                    uint32_t addr = base + swz((b_row + ns * 8) * 128u + (4u * h + b_cadd) * 16u);
                    ldsm4(addr, B[sp][ns][2 * h][0], B[sp][ns][2 * h][1],
                                B[sp][ns][2 * h + 1][0], B[sp][ns][2 * h + 1][1]);
                }
            }
        }
        // en values for this warp's lane columns (2 cols per ns)
        float enr[4][2];
#pragma unroll
        for (int ns = 0; ns < 4; ns++) {
            int kb = c * 128 + ng * 32 + ns * 8 + 2 * (l & 3);
            enr[ns][0] = g_en[kb];
            enr[ns][1] = g_en[kb + 1];
        }

#pragma unroll
        for (int mt = 0; mt < 4; mt++) {
            uint32_t A_[2][4][4];
            uint32_t rbase = (uint32_t)(mg * 64 + mt * 16) + a_row;
#pragma unroll
            for (int sp = 0; sp < 2; sp++) {
                uint32_t base = sb + (sp ? XLO : XHI);
#pragma unroll
                for (int ks = 0; ks < 4; ks++) {
                    uint32_t addr = base + swz(rbase * 128u + (2u * ks + a_cadd) * 16u);
                    ldsm4(addr, A_[sp][ks][0], A_[sp][ks][1], A_[sp][ks][2], A_[sp][ks][3]);
                }
            }
#pragma unroll
            for (int ns = 0; ns < 4; ns++) {
                float d0 = 0.f, d1 = 0.f, d2 = 0.f, d3 = 0.f;
#pragma unroll
                for (int ks = 0; ks < 4; ks++)
                    mma_bf16(d0, d1, d2, d3, A_[0][ks][0], A_[0][ks][1], A_[0][ks][2], A_[0][ks][3],
                             B[0][ns][ks][0], B[0][ns][ks][1]);
#pragma unroll
                for (int ks = 0; ks < 4; ks++)
                    mma_bf16(d0, d1, d2, d3, A_[0][ks][0], A_[0][ks][1], A_[0][ks][2], A_[0][ks][3],
                             B[1][ns][ks][0], B[1][ns][ks][1]);
#pragma unroll
                for (int ks = 0; ks < 4; ks++)
                    mma_bf16(d0, d1, d2, d3, A_[1][ks][0], A_[1][ks][1], A_[1][ks][2], A_[1][ks][3],
                             B[0][ns][ks][0], B[0][ns][ks][1]);

                int kb = c * 128 + ng * 32 + ns * 8 + 2 * (l & 3);
                float v0 = fmaf(-2.f, d0, enr[ns][0]);
                float v1 = fmaf(-2.f, d1, enr[ns][1]);
                float v2 = fmaf(-2.f, d2, enr[ns][0]);
                float v3 = fmaf(-2.f, d3, enr[ns][1]);
                int s0 = mt * 2, s1 = mt * 2 + 1;
                if (v0 < bestd[s0]) { best2[s0] = bestd[s0]; bestd[s0] = v0; bestk[s0] = kb; }
                else if (v0 < best2[s0]) best2[s0] = v0;
                if (v1 < bestd[s0]) { best2[s0] = bestd[s0]; bestd[s0] = v1; bestk[s0] = kb + 1; }
                else if (v1 < best2[s0]) best2[s0] = v1;
                if (v2 < bestd[s1]) { best2[s1] = bestd[s1]; bestd[s1] = v2; bestk[s1] = kb; }
                else if (v2 < best2[s1]) best2[s1] = v2;
                if (v3 < bestd[s1]) { best2[s1] = bestd[s1]; bestd[s1] = v3; bestk[s1] = kb + 1; }
                else if (v3 < best2[s1]) best2[s1] = v3;
            }
        }
    }

    // ---- butterfly over the 4 column-lanes (l&3) ----------------------------
#pragma unroll
    for (int st = 1; st <= 2; st <<= 1) {
#pragma unroll
        for (int s = 0; s < 8; s++) {
            float od = __shfl_xor_sync(0xFFFFFFFFu, bestd[s], st);
            float o2 = __shfl_xor_sync(0xFFFFFFFFu, best2[s], st);
            int   ok = __shfl_xor_sync(0xFFFFFFFFu, bestk[s], st);
            if (od < bestd[s]) { best2[s] = fminf(bestd[s], o2); bestd[s] = od; bestk[s] = ok; }
            else               { best2[s] = fminf(best2[s], od); }
        }
    }
    if ((l & 3) == 0) {
#pragma unroll
        for (int s = 0; s < 8; s++) {
            int row = mg * 64 + (s >> 1) * 16 + (l >> 2) + (s & 1) * 8;
            sval[ng][row] = bestd[s]; ssec[ng][row] = best2[s]; sidxr[ng][row] = bestk[s];
        }
    }
    __syncthreads();

    // ---- per-row reduce over 4 column-groups, write idx/flags ---------------
    if (t < 128) {
        float bd = sval[0][t], b2 = ssec[0][t];
        int bk = sidxr[0][t];
#pragma unroll
        for (int g = 1; g < 4; g++) {
            float od = sval[g][t], o2 = ssec[g][t];
            int ok = sidxr[g][t];
            if (od < bd) { b2 = fminf(bd, o2); bd = od; bk = ok; }
            else         { b2 = fminf(b2, od); }
        }
        g_idx[n0 + t] = bk;
        sidxf[t] = bk;
        if (b2 - bd < GEPS) {
            int p = atomicAdd(&g_nflag, 1);
            g_flaglist[p] = n0 + t;
        }
    }
    __syncthreads();

    // ---- encoded one-hot store: 128 rows x 1024 floats ----------------------
    {
        float2* e2 = (float2*)enc;
        size_t base = (size_t)blockIdx.x * 128 * 512;
        for (int i = t; i < 128 * 512; i += 256) {
            int r = i >> 9, s = i & 511;
            int id = sidxf[r];
            float2 v = make_float2(0.f, 0.f);
            if ((id >> 1) == s) { if (id & 1) v.y = 1.f; else v.x = 1.f; }
            __stcs(&e2[base + i], v);
        }
    }
}

// ---- K3: exact fp32 recompute for near-tie rows; fix idx + encoded ----------
__global__ __launch_bounds__(128) void vq_repair(const float* __restrict__ x,
                                                 const float* __restrict__ emb,
                                                 float* __restrict__ enc) {
    __shared__ float sx[DDIM];
    __shared__ float sval[128];
    __shared__ int   sidx[128];
    int t = threadIdx.x;
    int nf = g_nflag;
    for (int f = blockIdx.x; f < nf; f += gridDim.x) {
        int n = g_flaglist[f];
        int b = n >> 10, hw = n & 1023;
        if (t < DDIM) sx[t] = x[(size_t)b * 65536 + t * 1024 + hw];
        __syncthreads();
        float rn = g_rn[n];
        float bd = 3.4e38f; int bk = 0;
#pragma unroll 1
        for (int kk = 0; kk < 8; kk++) {
            int k = t * 8 + kk;
            const float* e = emb + k * DDIM;
            float dot = 0.f;
#pragma unroll
            for (int d = 0; d < DDIM; d++) dot = fmaf(sx[d], e[d], dot);
            float dist = fmaf(-2.f, dot, rn + g_en[k]);
            if (dist < bd) { bd = dist; bk = k; }
        }
        sval[t] = bd; sidx[t] = bk;
        __syncthreads();
        for (int s = 64; s; s >>= 1) {
            if (t < s) {
                if (sval[t + s] < sval[t] ||
                    (sval[t + s] == sval[t] && sidx[t + s] < sidx[t])) {
                    sval[t] = sval[t + s]; sidx[t] = sidx[t + s];
                }
            }
            __syncthreads();
        }
        if (t == 0) {
            int newk = sidx[0], oldk = g_idx[n];
            if (newk != oldk) {
                g_idx[n] = newk;
                enc[(size_t)n * 1024 + oldk] = 0.f;
                enc[(size_t)n * 1024 + newk] = 1.f;
            }
        }
        __syncthreads();
    }
}

// ---- K4: slim epilogue — counts, out, mse -----------------------------------
__global__ __launch_bounds__(128) void vq_epi(const float* __restrict__ x,
                                              const float* __restrict__ emb,
                                              float* __restrict__ out) {
    __shared__ float sred[4];
    int t = threadIdx.x;
    int b = blockIdx.x >> 3;
    int hw = (blockIdx.x & 7) * 128 + t;
    int n = blockIdx.x * 128 + t;
    int k = g_idx[n];
    atomicAdd(&g_counts[k], 1);

    const float* xb = x + (size_t)b * 65536 + hw;
    float* ob = out + (size_t)b * 65536 + hw;
    const float* eb = emb + (size_t)k * DDIM;
    float lm = 0.f;
#pragma unroll 8
    for (int d = 0; d < DDIM; d++) {
        float xv = xb[(size_t)d * 1024];
        float q  = eb[d];
        float df = q - xv;
        ob[(size_t)d * 1024] = xv + df;
        lm = fmaf(df, df, lm);
    }
#pragma unroll
    for (int o = 16; o; o >>= 1) lm += __shfl_xor_sync(0xFFFFFFFFu, lm, o);
    if ((t & 31) == 0) sred[t >> 5] = lm;
    __syncthreads();
    if (t == 0) atomicAdd(&g_mse, sred[0] + sred[1] + sred[2] + sred[3]);
}

// ---- K5: losses + perplexity -------------------------------------------------
__global__ void vq_fin(float* __restrict__ d_out) {
    __shared__ float sred[32];
    int k = threadIdx.x;
    float p = (float)g_counts[k] / 32768.f;
    float s = p * logf(p + 1e-10f);
#pragma unroll
    for (int o = 16; o; o >>= 1) s += __shfl_xor_sync(0xFFFFFFFFu, s, o);
    if ((k & 31) == 0) sred[k >> 5] = s;
    __syncthreads();
    if (k < 32) {
        float v = sred[k];
#pragma unroll
        for (int o = 16; o; o >>= 1) v += __shfl_xor_sync(0xFFFFFFFFu, v, o);
        if (k == 0) {
            float m = g_mse / 2097152.f;
            d_out[2097152] = m + 0.25f * m;
            d_out[2097153] = expf(-v);
        }
    }
}

extern "C" void kernel_launch(void* const* d_in, const int* in_sizes, int n_in,
                              void* d_out, int out_size) {
    const float* x   = (const float*)d_in[0];
    const float* emb = (const float*)d_in[1];
    float* out = (float*)d_out;
    float* enc = out + 2097154;

    cudaFuncSetAttribute(vq_gemm, cudaFuncAttributeMaxDynamicSharedMemorySize, DYNSM);

    vq_prep<<<64, 128>>>(emb);
    vq_gemm<<<256, 256, DYNSM>>>(x, enc);
    vq_repair<<<64, 128>>>(x, emb, enc);
    vq_epi<<<256, 128>>>(x, emb, out);
    vq_fin<<<1, 1024>>>(out);
}

// round 4
// speedup vs baseline: 1.3693x; 1.3693x over previous
#include <cuda_runtime.h>
#include <cuda_bf16.h>
#include <cstdint>

// VectorQuantizer forward — HMMA 3-split bf16, fused epilogue, occ-2.
// Inputs:  d_in[0] = x [32,64,32,32] fp32;  d_in[1] = emb_w [1024,64] fp32
// Output fp32: [0..2097151] out, [2097152] vq_loss, [2097153] perplexity,
//              [2097154..] encoded one-hot [32768,1024]

#define NVEC   32768
#define KCODES 1024
#define DDIM   64
#define GEPS   2e-5f

__device__ float g_en[KCODES];
__device__ int   g_counts[KCODES];
__device__ float g_mse;
__device__ int   g_idx[NVEC];
__device__ float g_rn[NVEC];
__device__ float g_bd[NVEC];
__device__ int   g_nflag;
__device__ int   g_flaglist[NVEC];
__device__ uint4 g_ehi4[8192];   // emb bf16-hi, SW128-swizzled image (128KB)
__device__ uint4 g_elo4[8192];   // emb bf16-lo

__device__ __forceinline__ uint32_t smem_u32(const void* p) {
    uint32_t a;
    asm("{ .reg .u64 t; cvta.to.shared.u64 t, %1; cvt.u32.u64 %0, t; }" : "=r"(a) : "l"(p));
    return a;
}
__device__ __forceinline__ uint32_t swz(uint32_t off) { return off ^ ((off >> 3) & 0x70); }

__device__ __forceinline__ void ldsm4(uint32_t a, uint32_t& r0, uint32_t& r1,
                                      uint32_t& r2, uint32_t& r3) {
    asm volatile("ldmatrix.sync.aligned.m8n8.x4.shared.b16 {%0,%1,%2,%3}, [%4];"
                 : "=r"(r0), "=r"(r1), "=r"(r2), "=r"(r3) : "r"(a));
}
__device__ __forceinline__ void mma_bf16(float* d,
                                         uint32_t a0, uint32_t a1, uint32_t a2, uint32_t a3,
                                         uint32_t b0, uint32_t b1) {
    asm volatile("mma.sync.aligned.m16n8k16.row.col.f32.bf16.bf16.f32 "
                 "{%0,%1,%2,%3}, {%4,%5,%6,%7}, {%8,%9}, {%0,%1,%2,%3};"
                 : "+f"(d[0]), "+f"(d[1]), "+f"(d[2]), "+f"(d[3])
                 : "r"(a0), "r"(a1), "r"(a2), "r"(a3), "r"(b0), "r"(b1));
}
__device__ __forceinline__ void bf16split(float v, uint16_t& h, uint16_t& l) {
    __nv_bfloat16 hb = __float2bfloat16(v);
    __nv_bfloat16 lb = __float2bfloat16(v - __bfloat162float(hb));
    h = __bfloat16_as_ushort(hb);
    l = __bfloat16_as_ushort(lb);
}
__device__ __forceinline__ void cpa16(uint32_t s, const void* g) {
    asm volatile("cp.async.cg.shared.global [%0], [%1], 16;" :: "r"(s), "l"(g));
}
#define CPA_COMMIT() asm volatile("cp.async.commit_group;" ::: "memory")

// dynamic smem layout
#define EBUF(buf)   ((buf) * 16384)              // hi 8K, lo 8K per buffer
#define SENO(buf)   (32768 + (buf) * 256)
#define XHI         33792
#define XLO         50176
#define DYNSM       66560

// ---- K1: emb -> bf16 hi/lo swizzled image; ||e||^2; zero accums -------------
__global__ __launch_bounds__(128) void vq_prep(const float* __restrict__ emb) {
    int t = threadIdx.x;
    int code = blockIdx.x * 16 + (t >> 3);
    int ch = t & 7;
    const float* e = emb + code * DDIM + ch * 8;
    float4 a = *(const float4*)e, b = *(const float4*)(e + 4);
    float v[8] = {a.x, a.y, a.z, a.w, b.x, b.y, b.z, b.w};
    float s = 0.f;
    uint32_t hw[4], lw[4];
#pragma unroll
    for (int p = 0; p < 4; p++) {
        float v0 = v[2 * p], v1 = v[2 * p + 1];
        s = fmaf(v0, v0, s); s = fmaf(v1, v1, s);
        uint16_t h0, l0, h1, l1;
        bf16split(v0, h0, l0); bf16split(v1, h1, l1);
        hw[p] = (uint32_t)h0 | ((uint32_t)h1 << 16);
        lw[p] = (uint32_t)l0 | ((uint32_t)l1 << 16);
    }
    uint32_t off = swz((uint32_t)code * 128u + (uint32_t)ch * 16u) >> 4;
    g_ehi4[off] = make_uint4(hw[0], hw[1], hw[2], hw[3]);
    g_elo4[off] = make_uint4(lw[0], lw[1], lw[2], lw[3]);
    s += __shfl_xor_sync(0xFFFFFFFFu, s, 1);
    s += __shfl_xor_sync(0xFFFFFFFFu, s, 2);
    s += __shfl_xor_sync(0xFFFFFFFFu, s, 4);
    if (ch == 0) { g_en[code] = s; g_counts[code] = 0; }
    if (blockIdx.x == 0 && t == 0) { g_mse = 0.f; g_nflag = 0; }
}

// ---- K2: HMMA GEMM + argmin + fused epilogue --------------------------------
__global__ __launch_bounds__(256, 2) void vq_gemm(const float* __restrict__ x,
                                                  const float* __restrict__ emb,
                                                  float* __restrict__ out,
                                                  float* __restrict__ enc) {
    extern __shared__ __align__(1024) char dsm[];
    __shared__ float srn[256];
    __shared__ float srnf[128];
    __shared__ int   sidxf[128];
    __shared__ float sbd[128];

    const int t = threadIdx.x;
    const int l = t & 31;
    const int w = t >> 5;                 // warp 0..7 -> rows w*16..+15
    const int n0 = blockIdx.x * 128;
    const int b  = blockIdx.x >> 3;
    const int hw0 = (blockIdx.x & 7) * 128;
    const uint32_t sb = smem_u32(dsm);

    // kick off e-chunk prefetch for chunks 0 and 1 (overlaps x staging)
    {
        const uint4* gh0 = g_ehi4;       const uint4* gl0 = g_elo4;
        uint32_t bh = sb + EBUF(0);
        cpa16(bh + t * 16, gh0 + t);              cpa16(bh + (t + 256) * 16, gh0 + t + 256);
        cpa16(bh + 8192 + t * 16, gl0 + t);       cpa16(bh + 8192 + (t + 256) * 16, gl0 + t + 256);
        if (t < 16) cpa16(sb + SENO(0) + t * 16, (const char*)g_en + t * 16);
        CPA_COMMIT();
        const uint4* gh1 = g_ehi4 + 512; const uint4* gl1 = g_elo4 + 512;
        uint32_t bh1 = sb + EBUF(1);
        cpa16(bh1 + t * 16, gh1 + t);             cpa16(bh1 + (t + 256) * 16, gh1 + t + 256);
        cpa16(bh1 + 8192 + t * 16, gl1 + t);      cpa16(bh1 + 8192 + (t + 256) * 16, gl1 + t + 256);
        if (t < 16) cpa16(sb + SENO(1) + t * 16, (const char*)g_en + 256 + t * 16);
        CPA_COMMIT();
    }

    // ---- stage x tile (2 threads per row), bf16 split, swizzled -------------
    {
        int row = t & 127, half = t >> 7;
        const float* xb = x + (size_t)b * 65536 + hw0 + row;
        float rp = 0.f;
#pragma unroll
        for (int jj = 0; jj < 4; jj++) {
            int j = half * 4 + jj;
            float v[8];
#pragma unroll
            for (int i = 0; i < 8; i++) v[i] = xb[(size_t)(j * 8 + i) * 1024];
#pragma unroll
            for (int i = 0; i < 8; i++) rp = fmaf(v[i], v[i], rp);
            uint32_t hw_[4], lw_[4];
#pragma unroll
            for (int p = 0; p < 4; p++) {
                uint16_t h0, l0, h1, l1;
                bf16split(v[2 * p], h0, l0); bf16split(v[2 * p + 1], h1, l1);
                hw_[p] = (uint32_t)h0 | ((uint32_t)h1 << 16);
                lw_[p] = (uint32_t)l0 | ((uint32_t)l1 << 16);
            }
            uint32_t off = swz((uint32_t)row * 128u + (uint32_t)j * 16u);
            *(uint4*)(dsm + XHI + off) = make_uint4(hw_[0], hw_[1], hw_[2], hw_[3]);
            *(uint4*)(dsm + XLO + off) = make_uint4(lw_[0], lw_[1], lw_[2], lw_[3]);
        }
        srn[t] = rp;
    }
    __syncthreads();
    if (t < 128) {
        float full = srn[t] + srn[t + 128];
        srnf[t] = full;
        g_rn[n0 + t] = full;
    }
    __syncthreads();

    // ---- persistent A fragments (warp rows w*16..+15, k=64, 2 splits) -------
    uint32_t Af[2][4][4];
    {
        uint32_t a_row = (uint32_t)(l & 15);
        uint32_t a_cadd = (uint32_t)(l >> 4);
        uint32_t rbase = (uint32_t)(w * 16) + a_row;
#pragma unroll
        for (int sp = 0; sp < 2; sp++) {
            uint32_t base = sb + (sp ? XLO : XHI);
#pragma unroll
            for (int ks = 0; ks < 4; ks++) {
                uint32_t addr = base + swz(rbase * 128u + (2u * ks + a_cadd) * 16u);
                ldsm4(addr, Af[sp][ks][0], Af[sp][ks][1], Af[sp][ks][2], Af[sp][ks][3]);
            }
        }
    }
    const float rnA = srnf[w * 16 + (l >> 2)];
    const float rnB = srnf[w * 16 + (l >> 2) + 8];

    float bestdA = 3.4e38f, best2A = 3.4e38f;
    float bestdB = 3.4e38f, best2B = 3.4e38f;
    int bestkA = 0, bestkB = 0;

    const uint32_t b_o1 = ((uint32_t)(l & 7)) * 128u;      // row part; +n8*1024 later
    float2* e2 = (float2*)enc;

#pragma unroll 1
    for (int c = 0; c < 16; c++) {
        if (c < 15) asm volatile("cp.async.wait_group 1;" ::: "memory");
        else        asm volatile("cp.async.wait_group 0;" ::: "memory");
        __syncthreads();

        const int buf = c & 1;
        const uint32_t ebh = sb + EBUF(buf);
        const uint32_t ebl = ebh + 8192;
        const float2* senp = (const float2*)(dsm + SENO(buf));

#pragma unroll
        for (int n8 = 0; n8 < 8; n8++) {
            uint32_t ro = (uint32_t)n8 * 1024u + b_o1;
            uint32_t o1 = swz(ro + ((uint32_t)(l >> 3)) * 16u);
            uint32_t o2 = swz(ro + (4u + (uint32_t)(l >> 3)) * 16u);
            uint32_t bh[8], bl[8];
            ldsm4(ebh + o1, bh[0], bh[1], bh[2], bh[3]);
            ldsm4(ebh + o2, bh[4], bh[5], bh[6], bh[7]);
            ldsm4(ebl + o1, bl[0], bl[1], bl[2], bl[3]);
            ldsm4(ebl + o2, bl[4], bl[5], bl[6], bl[7]);

            float dhh[4] = {0.f, 0.f, 0.f, 0.f};
            float dhl[4] = {0.f, 0.f, 0.f, 0.f};
            float dlh[4] = {0.f, 0.f, 0.f, 0.f};
#pragma unroll
            for (int ks = 0; ks < 4; ks++) {
                mma_bf16(dhh, Af[0][ks][0], Af[0][ks][1], Af[0][ks][2], Af[0][ks][3],
                         bh[2 * ks], bh[2 * ks + 1]);
                mma_bf16(dhl, Af[0][ks][0], Af[0][ks][1], Af[0][ks][2], Af[0][ks][3],
                         bl[2 * ks], bl[2 * ks + 1]);
                mma_bf16(dlh, Af[1][ks][0], Af[1][ks][1], Af[1][ks][2], Af[1][ks][3],
                         bh[2 * ks], bh[2 * ks + 1]);
            }
            float2 en2 = senp[n8 * 4 + (l & 3)];
            int kb = c * 64 + n8 * 8 + 2 * (l & 3);
            float v0 = fmaf(-2.f, (dhh[0] + dhl[0]) + dlh[0], rnA + en2.x);
            float v1 = fmaf(-2.f, (dhh[1] + dhl[1]) + dlh[1], rnA + en2.y);
            float v2 = fmaf(-2.f, (dhh[2] + dhl[2]) + dlh[2], rnB + en2.x);
            float v3 = fmaf(-2.f, (dhh[3] + dhl[3]) + dlh[3], rnB + en2.y);
            if (v0 < bestdA) { best2A = bestdA; bestdA = v0; bestkA = kb; }
            else if (v0 < best2A) best2A = v0;
            if (v1 < bestdA) { best2A = bestdA; bestdA = v1; bestkA = kb + 1; }
            else if (v1 < best2A) best2A = v1;
            if (v2 < bestdB) { best2B = bestdB; bestdB = v2; bestkB = kb; }
            else if (v2 < best2B) best2B = v2;
            if (v3 < bestdB) { best2B = bestdB; bestdB = v3; bestkB = kb + 1; }
            else if (v3 < best2B) best2B = v3;
        }

        // stream one-hot ZEROS for this 64-col block (overwritten by 1s later)
        {
            float2 z = make_float2(0.f, 0.f);
            size_t colb = (size_t)c * 32 + l;
#pragma unroll
            for (int r = 0; r < 16; r++)
                __stcs(&e2[(size_t)(n0 + w * 16 + r) * 512 + colb], z);
        }
        __syncthreads();

        if (c + 2 < 16) {
            const uint4* gh = g_ehi4 + (c + 2) * 512;
            const uint4* gl = g_elo4 + (c + 2) * 512;
            uint32_t bh2 = sb + EBUF(buf);
            cpa16(bh2 + t * 16, gh + t);             cpa16(bh2 + (t + 256) * 16, gh + t + 256);
            cpa16(bh2 + 8192 + t * 16, gl + t);      cpa16(bh2 + 8192 + (t + 256) * 16, gl + t + 256);
            if (t < 16) cpa16(sb + SENO(buf) + t * 16, (const char*)g_en + (c + 2) * 256 + t * 16);
            CPA_COMMIT();
        }
    }

    // ---- per-row reduce over the 4 column-lanes -----------------------------
#pragma unroll
    for (int st = 1; st <= 2; st <<= 1) {
        float od = __shfl_xor_sync(0xFFFFFFFFu, bestdA, st);
        float o2 = __shfl_xor_sync(0xFFFFFFFFu, best2A, st);
        int   ok = __shfl_xor_sync(0xFFFFFFFFu, bestkA, st);
        if (od < bestdA) { best2A = fminf(bestdA, o2); bestdA = od; bestkA = ok; }
        else             { best2A = fminf(best2A, od); }
        od = __shfl_xor_sync(0xFFFFFFFFu, bestdB, st);
        o2 = __shfl_xor_sync(0xFFFFFFFFu, best2B, st);
        ok = __shfl_xor_sync(0xFFFFFFFFu, bestkB, st);
        if (od < bestdB) { best2B = fminf(bestdB, o2); bestdB = od; bestkB = ok; }
        else             { best2B = fminf(best2B, od); }
    }
    if ((l & 3) == 0) {
        int rA = w * 16 + (l >> 2), rB = rA + 8;
        sidxf[rA] = bestkA; sbd[rA] = bestdA;
        sidxf[rB] = bestkB; sbd[rB] = bestdB;
        g_idx[n0 + rA] = bestkA; g_bd[n0 + rA] = bestdA;
        g_idx[n0 + rB] = bestkB; g_bd[n0 + rB] = bestdB;
        if (best2A - bestdA < GEPS) { int p = atomicAdd(&g_nflag, 1); g_flaglist[p] = n0 + rA; }
        if (best2B - bestdB < GEPS) { int p = atomicAdd(&g_nflag, 1); g_flaglist[p] = n0 + rB; }
    }
    __syncthreads();

    // ---- fused epilogue: ones, out rows, counts, mse ------------------------
    if (t < 128) {
        enc[(size_t)(n0 + t) * 1024 + sidxf[t]] = 1.f;
        atomicAdd(&g_counts[sidxf[t]], 1);
    }
    {
        int row = t & 127, half = t >> 7;
        int k = sidxf[row];
        const float* er = emb + (size_t)k * 64 + half * 32;
        const float* xr = x   + (size_t)b * 65536 + (size_t)(half * 32) * 1024 + hw0 + row;
        float*       orow = out + (size_t)b * 65536 + (size_t)(half * 32) * 1024 + hw0 + row;
#pragma unroll 8
        for (int i = 0; i < 32; i++) {
            float xv = xr[(size_t)i * 1024];
            float q  = er[i];
            orow[(size_t)i * 1024] = xv + (q - xv);
        }
    }
    if (t < 32) {
        float s = sbd[t] + sbd[t + 32] + sbd[t + 64] + sbd[t + 96];
#pragma unroll
        for (int o = 16; o; o >>= 1) s += __shfl_xor_sync(0xFFFFFFFFu, s, o);
        if (t == 0) atomicAdd(&g_mse, s);
    }
}

// ---- K3: exact fp32 recompute for near-tie rows; patch everything ----------
__global__ __launch_bounds__(128) void vq_repair(const float* __restrict__ x,
                                                 const float* __restrict__ emb,
                                                 float* __restrict__ out,
                                                 float* __restrict__ enc) {
    __shared__ float sx[DDIM];
    __shared__ float sval[128];
    __shared__ int   sidx[128];
    int t = threadIdx.x;
    int nf = g_nflag;
    for (int f = blockIdx.x; f < nf; f += gridDim.x) {
        int n = g_flaglist[f];
        int b = n >> 10, hw = n & 1023;
        if (t < DDIM) sx[t] = x[(size_t)b * 65536 + t * 1024 + hw];
        __syncthreads();
        float rn = g_rn[n];
        float bd = 3.4e38f; int bk = 0;
#pragma unroll 1
        for (int kk = 0; kk < 8; kk++) {
            int k = t * 8 + kk;
            const float* e = emb + k * DDIM;
            float dot = 0.f;
#pragma unroll
            for (int d = 0; d < DDIM; d++) dot = fmaf(sx[d], e[d], dot);
            float dist = fmaf(-2.f, dot, rn + g_en[k]);
            if (dist < bd) { bd = dist; bk = k; }
        }
        sval[t] = bd; sidx[t] = bk;
        __syncthreads();
        for (int s = 64; s; s >>= 1) {
            if (t < s) {
                if (sval[t + s] < sval[t] ||
                    (sval[t + s] == sval[t] && sidx[t + s] < sidx[t])) {
                    sval[t] = sval[t + s]; sidx[t] = sidx[t + s];
                }
            }
            __syncthreads();
        }
        int newk = sidx[0];
        float newbd = sval[0];
        int oldk = g_idx[n];
        if (t == 0) {
            atomicAdd(&g_mse, newbd - g_bd[n]);   // refine loss for this row
            if (newk != oldk) {
                g_idx[n] = newk;
                enc[(size_t)n * 1024 + oldk] = 0.f;
                enc[(size_t)n * 1024 + newk] = 1.f;
                atomicSub(&g_counts[oldk], 1);
                atomicAdd(&g_counts[newk], 1);
            }
        }
        if (newk != oldk && t < DDIM) {
            float xv = sx[t];
            float q  = emb[(size_t)newk * DDIM + t];
            out[(size_t)b * 65536 + t * 1024 + hw] = xv + (q - xv);
        }
        __syncthreads();
    }
}

// ---- K4: losses + perplexity -------------------------------------------------
__global__ void vq_fin(float* __restrict__ d_out) {
    __shared__ float sred[32];
    int k = threadIdx.x;
    float p = (float)g_counts[k] / 32768.f;
    float s = p * logf(p + 1e-10f);
#pragma unroll
    for (int o = 16; o; o >>= 1) s += __shfl_xor_sync(0xFFFFFFFFu, s, o);
    if ((k & 31) == 0) sred[k >> 5] = s;
    __syncthreads();
    if (k < 32) {
        float v = sred[k];
#pragma unroll
        for (int o = 16; o; o >>= 1) v += __shfl_xor_sync(0xFFFFFFFFu, v, o);
        if (k == 0) {
            float m = g_mse / 2097152.f;
            d_out[2097152] = m + 0.25f * m;
            d_out[2097153] = expf(-v);
        }
    }
}

extern "C" void kernel_launch(void* const* d_in, const int* in_sizes, int n_in,
                              void* d_out, int out_size) {
    const float* x   = (const float*)d_in[0];
    const float* emb = (const float*)d_in[1];
    float* out = (float*)d_out;
    float* enc = out + 2097154;

    cudaFuncSetAttribute(vq_gemm, cudaFuncAttributeMaxDynamicSharedMemorySize, DYNSM);

    vq_prep<<<64, 128>>>(emb);
    vq_gemm<<<256, 256, DYNSM>>>(x, emb, out, enc);
    vq_repair<<<64, 128>>>(x, emb, out, enc);
    vq_fin<<<1, 1024>>>(out);
}